// round 1
// baseline (speedup 1.0000x reference)
#include <cuda_runtime.h>

// Problem constants (fixed by the reference)
#define NN        10000            // nodes
#define DEG       32
#define CH        16
#define INDIM     4
#define BATCH     8
#define E_EDGES   (NN * DEG)       // 320000
#define WSTRIDE   (E_EDGES * CH)   // 5120000 floats between weight[i] planes
#define OUTPLANE  (NN * CH)        // 160000 floats per batch in output

// Scratch (allocation-free: __device__ globals)
__device__ int   g_flag = 0;                  // 1 if edges buffer is int32, 0 if int64
__device__ float g_xT[(NN + 1) * 32];         // [node][b*4+i], row NN = zeros (pad)
__device__ int   g_e32[E_EDGES];              // edges narrowed to int32

// ---------------------------------------------------------------------------
// Prep 1: build transposed/padded x, and detect edges dtype (int64 vs int32).
// For int64 data every odd int32 slot (high word) is 0; sample 256 spread slots.
// ---------------------------------------------------------------------------
__global__ void prep_xT_detect(const float* __restrict__ x,
                               const int*   __restrict__ e_as_i32) {
    int tid = blockIdx.x * blockDim.x + threadIdx.x;

    if (tid < (NN + 1) * 32) {
        int node = tid >> 5;
        int k    = tid & 31;        // k = b*4 + i
        float v  = 0.0f;
        if (node < NN) {
            int b = k >> 2, i = k & 3;
            v = x[(b * NN + node) * INDIM + i];
        }
        g_xT[tid] = v;
    }

    if (tid < 256) {
        // sample odd int32 slots across the first 320000 int32 words
        int slot = 2 * (tid * 625) + 1;   // max 318751, in-bounds for both layouts
        if (e_as_i32[slot] != 0) atomicOr(&g_flag, 1);
    }
}

// ---------------------------------------------------------------------------
// Prep 2: narrow edges to int32 using the detected layout.
// ---------------------------------------------------------------------------
__global__ void prep_edges(const void* __restrict__ edges) {
    int t = blockIdx.x * blockDim.x + threadIdx.x;
    if (t < E_EDGES) {
        int v;
        if (g_flag) v = ((const int*)edges)[t];
        else        v = (int)(((const long long*)edges)[t]);
        g_e32[t] = v;
    }
}

// ---------------------------------------------------------------------------
// Main kernel: one warp per node.
//   lane = 16*dhalf + c  (dhalf in {0,1}, c in 0..15)
//   iteration t handles d = 2t + dhalf, t = 0..15
//   gather index j = 512*(n mod 625) + 32t + lane   (exact, no wrap — E=512*625)
//   weight index  = i*WSTRIDE + 512*n + 32t + lane  (coalesced 128B/warp per i)
// ---------------------------------------------------------------------------
__global__ __launch_bounds__(256, 4)
void lcg_main(const float* __restrict__ W, float* __restrict__ out) {
    int gwarp = (blockIdx.x * blockDim.x + threadIdx.x) >> 5;
    int lane  = threadIdx.x & 31;
    if (gwarp >= NN) return;
    const int n = gwarp;

    const int jbase = 512 * (n % 625) + lane;   // edge-gather base (L2-resident)
    const int wbase = 512 * n + lane;           // weight base (streaming)

    float acc[BATCH];
#pragma unroll
    for (int b = 0; b < BATCH; ++b) acc[b] = 0.0f;

#pragma unroll 4
    for (int t = 0; t < 16; ++t) {
        const int off = 32 * t;
        const int src = __ldg(&g_e32[jbase + off]);

        const int wo = wbase + off;
        const float w0 = __ldcs(W + wo);
        const float w1 = __ldcs(W + wo + WSTRIDE);
        const float w2 = __ldcs(W + wo + 2 * WSTRIDE);
        const float w3 = __ldcs(W + wo + 3 * WSTRIDE);

        // 8 batches: one float4 each, all inside a single 128B line of g_xT
        const float4* __restrict__ xp =
            reinterpret_cast<const float4*>(g_xT + src * 32);
#pragma unroll
        for (int b = 0; b < BATCH; ++b) {
            float4 v = xp[b];   // (x[b,src,0..3])
            acc[b] += v.x * w0 + v.y * w1 + v.z * w2 + v.w * w3;
        }
    }

    // combine the two d-halves (lane <-> lane^16)
#pragma unroll
    for (int b = 0; b < BATCH; ++b)
        acc[b] += __shfl_xor_sync(0xffffffffu, acc[b], 16);

    const int c    = lane & 15;
    const int half = lane >> 4;          // 0 -> batches 0..3, 1 -> batches 4..7
    const int obase = n * CH + c;
#pragma unroll
    for (int k = 0; k < 4; ++k) {
        float v = (half == 0) ? acc[k] : acc[k + 4];
        out[(half * 4 + k) * OUTPLANE + obase] = v;
    }
}

// ---------------------------------------------------------------------------
// Launch
// ---------------------------------------------------------------------------
extern "C" void kernel_launch(void* const* d_in, const int* in_sizes, int n_in,
                              void* d_out, int out_size) {
    const float* x     = (const float*)d_in[0];   // (8,10000,4) f32
    const void*  edges = d_in[1];                 // (320000,) int64 or int32
    const float* W     = (const float*)d_in[2];   // (4,320000,16) f32
    float*       out   = (float*)d_out;           // (8,10000,16) f32

    (void)in_sizes; (void)n_in; (void)out_size;

    prep_xT_detect<<<((NN + 1) * 32 + 255) / 256, 256>>>(x, (const int*)edges);
    prep_edges<<<(E_EDGES + 255) / 256, 256>>>(edges);

    // one warp per node: 10000 warps = 320000 threads
    lcg_main<<<(NN * 32 + 255) / 256, 256>>>(W, out);
}

// round 2
// speedup vs baseline: 2.1382x; 2.1382x over previous
#include <cuda_runtime.h>

// Problem constants (fixed by the reference)
#define NN        10000            // nodes
#define DEG       32
#define CH        16
#define INDIM     4
#define BATCH     8
#define E_EDGES   (NN * DEG)       // 320000 = 512 * 625
#define WSTRIDE   (E_EDGES * CH)   // 5120000 floats between weight[i] planes
#define OUTPLANE  (NN * CH)        // 160000 floats per batch in output
#define NRES      625              // residue classes: n mod 625
#define FLATS     512              // (d,c) pairs per node
#define ROWPAD    36               // smem row stride in floats (32 data + 4 pad)
#define SMEM_BYTES (FLATS * ROWPAD * 4)   // 73728 B

// Scratch (allocation-free: __device__ globals)
__device__ float g_xT[(NN + 1) * 32];   // [node][b*4+i], row NN = zeros (pad)
__device__ int   g_e32[E_EDGES];        // edges narrowed to int32

// ---------------------------------------------------------------------------
// Prep (single kernel): per-block int64/int32 detection (no cross-block dep),
// narrow edges to int32, build transposed padded x. Grid-stride for MLP.
// ---------------------------------------------------------------------------
__global__ void prep_kernel(const float* __restrict__ x,
                            const void*  __restrict__ edges) {
    __shared__ int s_is32;
    const int t = threadIdx.x;
    if (t == 0) s_is32 = 0;
    __syncthreads();
    if (t < 64) {
        // For int64 data every odd int32 word is a zero high-word (values<=10000).
        int slot = 2 * (t * 4999) + 1;          // < 640000, in-bounds both layouts
        if (((const int*)edges)[slot] != 0) atomicOr(&s_is32, 1);
    }
    __syncthreads();
    const bool is32 = (s_is32 != 0);

    const int gtid = blockIdx.x * blockDim.x + t;
    const int nth  = gridDim.x * blockDim.x;

    if (is32) {
        const int* e = (const int*)edges;
        for (int j = gtid; j < E_EDGES; j += nth) g_e32[j] = e[j];
    } else {
        const long long* e = (const long long*)edges;
        for (int j = gtid; j < E_EDGES; j += nth) g_e32[j] = (int)e[j];
    }

    for (int j = gtid; j < (NN + 1) * 32; j += nth) {
        int node = j >> 5;
        int k    = j & 31;                      // k = b*4 + i
        float v  = 0.0f;
        if (node < NN) v = x[((k >> 2) * NN + node) * INDIM + (k & 3)];
        g_xT[j] = v;
    }
}

// ---------------------------------------------------------------------------
// Main: one block per residue class r = n mod 625.
//   All 16 nodes {r + 625*j} share the same 512 gather rows:
//     src(flat) = e32[512*r + flat],  flat = 16*d + c.
//   Stage rows into smem coalesced (1 line / instruction), then 8 warps
//   compute 2 nodes each. Lane = (p = lane>>3: channel quad, b = lane&7).
// ---------------------------------------------------------------------------
__global__ __launch_bounds__(256, 3)
void lcg_main(const float* __restrict__ W, float* __restrict__ out) {
    extern __shared__ float sx[];               // [512][ROWPAD]
    const int r    = blockIdx.x;
    const int w    = threadIdx.x >> 5;          // warp 0..7
    const int lane = threadIdx.x & 31;

    // ---- Stage A: gather 512 x-rows into smem (warp w does rows w*64..+63)
    {
        const int fbase = w * 64;
        const int ev0 = g_e32[r * FLATS + fbase + lane];
        const int ev1 = g_e32[r * FLATS + fbase + 32 + lane];
#pragma unroll 4
        for (int k = 0; k < 64; ++k) {
            int src = __shfl_sync(0xffffffffu, (k < 32) ? ev0 : ev1, k & 31);
            float v = __ldg(&g_xT[src * 32 + lane]);     // one 128B line / warp
            sx[(fbase + k) * ROWPAD + lane] = v;
        }
    }
    __syncthreads();

    // ---- Stage B: compute. Warp w handles nodes nA = r+625*(2w), nB = nA+625.
    const int p = lane >> 3;                    // channel quad: c = 4p+m
    const int b = lane & 7;                     // batch

    const int nA = r + NRES * (2 * w);
    const int nB = nA + NRES;

    const float* __restrict__ WA = W + nA * FLATS + 4 * p;
    const float* __restrict__ WB = W + nB * FLATS + 4 * p;
    const float* __restrict__ xbase = sx + 4 * p * ROWPAD + 4 * b;

    float accA0 = 0.f, accA1 = 0.f, accA2 = 0.f, accA3 = 0.f;
    float accB0 = 0.f, accB1 = 0.f, accB2 = 0.f, accB3 = 0.f;

#pragma unroll 2
    for (int d = 0; d < DEG; ++d) {
        const int o = 16 * d;

        // x rows for channels c = 4p+m, m = 0..3 (shared by both nodes)
        const float* rp = xbase + o * ROWPAD;
        float4 x0 = *(const float4*)(rp);
        float4 x1 = *(const float4*)(rp + ROWPAD);
        float4 x2 = *(const float4*)(rp + 2 * ROWPAD);
        float4 x3 = *(const float4*)(rp + 3 * ROWPAD);

        // weights: component m of a_i is W[i][e(d), 4p+m]
        float4 a0 = __ldcs((const float4*)(WA + o));
        float4 a1 = __ldcs((const float4*)(WA + o + WSTRIDE));
        float4 a2 = __ldcs((const float4*)(WA + o + 2 * WSTRIDE));
        float4 a3 = __ldcs((const float4*)(WA + o + 3 * WSTRIDE));

        accA0 += x0.x * a0.x + x0.y * a1.x + x0.z * a2.x + x0.w * a3.x;
        accA1 += x1.x * a0.y + x1.y * a1.y + x1.z * a2.y + x1.w * a3.y;
        accA2 += x2.x * a0.z + x2.y * a1.z + x2.z * a2.z + x2.w * a3.z;
        accA3 += x3.x * a0.w + x3.y * a1.w + x3.z * a2.w + x3.w * a3.w;

        float4 b0 = __ldcs((const float4*)(WB + o));
        float4 b1 = __ldcs((const float4*)(WB + o + WSTRIDE));
        float4 b2 = __ldcs((const float4*)(WB + o + 2 * WSTRIDE));
        float4 b3 = __ldcs((const float4*)(WB + o + 3 * WSTRIDE));

        accB0 += x0.x * b0.x + x0.y * b1.x + x0.z * b2.x + x0.w * b3.x;
        accB1 += x1.x * b0.y + x1.y * b1.y + x1.z * b2.y + x1.w * b3.y;
        accB2 += x2.x * b0.z + x2.y * b1.z + x2.z * b2.z + x2.w * b3.z;
        accB3 += x3.x * b0.w + x3.y * b1.w + x3.z * b2.w + x3.w * b3.w;
    }

    // ---- Epilogue: lane (p,b) owns out[b, n, 4p..4p+3]
    *(float4*)(out + b * OUTPLANE + nA * CH + 4 * p) =
        make_float4(accA0, accA1, accA2, accA3);
    *(float4*)(out + b * OUTPLANE + nB * CH + 4 * p) =
        make_float4(accB0, accB1, accB2, accB3);
}

// ---------------------------------------------------------------------------
// Launch
// ---------------------------------------------------------------------------
extern "C" void kernel_launch(void* const* d_in, const int* in_sizes, int n_in,
                              void* d_out, int out_size) {
    const float* x     = (const float*)d_in[0];   // (8,10000,4) f32
    const void*  edges = d_in[1];                 // (320000,) int64 or int32
    const float* W     = (const float*)d_in[2];   // (4,320000,16) f32
    float*       out   = (float*)d_out;           // (8,10000,16) f32
    (void)in_sizes; (void)n_in; (void)out_size;

    // idempotent, deterministic; needed for 72KB dynamic smem
    cudaFuncSetAttribute(lcg_main, cudaFuncAttributeMaxDynamicSharedMemorySize,
                         SMEM_BYTES);

    prep_kernel<<<320, 256>>>(x, edges);
    lcg_main<<<NRES, 256, SMEM_BYTES>>>(W, out);
}

// round 3
// speedup vs baseline: 4.2783x; 2.0009x over previous
#include <cuda_runtime.h>

// Problem constants (fixed by the reference)
#define NN        10000            // nodes
#define DEG       32
#define CH        16
#define INDIM     4
#define BATCH     8
#define E_EDGES   (NN * DEG)       // 320000 = 512 * 625
#define WSTRIDE   (E_EDGES * CH)   // 5120000 floats between weight[i] planes
#define OUTPLANE  (NN * CH)        // 160000 floats per batch in output
#define NRES      625              // residue classes: n mod 625
#define FLATS     512              // (d,c) pairs per node
#define ROWPAD    36               // smem row stride (mult of 4 for float4 align)
#define SMEM_BYTES (FLATS * ROWPAD * 4)   // 73728 B -> 3 blocks/SM

// Scratch (allocation-free: __device__ globals)
__device__ float g_xT[(NN + 1) * 32];   // [node][b*4+i], row NN = zeros (pad)
__device__ int   g_e32[E_EDGES];        // edges narrowed to int32

// ---------------------------------------------------------------------------
// Prep: per-block int64/int32 detection, narrow edges, transpose/pad x.
// ---------------------------------------------------------------------------
__global__ void prep_kernel(const float* __restrict__ x,
                            const void*  __restrict__ edges) {
    __shared__ int s_is32;
    const int t = threadIdx.x;
    if (t == 0) s_is32 = 0;
    __syncthreads();
    if (t < 64) {
        // int64 data: every odd int32 word is a zero high-word (values<=10000)
        int slot = 2 * (t * 4999) + 1;
        if (((const int*)edges)[slot] != 0) atomicOr(&s_is32, 1);
    }
    __syncthreads();
    const bool is32 = (s_is32 != 0);

    const int gtid = blockIdx.x * blockDim.x + t;
    const int nth  = gridDim.x * blockDim.x;

    if (is32) {
        const int* e = (const int*)edges;
        for (int j = gtid; j < E_EDGES; j += nth) g_e32[j] = e[j];
    } else {
        const long long* e = (const long long*)edges;
        for (int j = gtid; j < E_EDGES; j += nth) g_e32[j] = (int)e[j];
    }

    for (int j = gtid; j < (NN + 1) * 32; j += nth) {
        int node = j >> 5;
        int k    = j & 31;                      // k = b*4 + i
        float v  = 0.0f;
        if (node < NN) v = x[((k >> 2) * NN + node) * INDIM + (k & 3)];
        g_xT[j] = v;
    }
}

// ---------------------------------------------------------------------------
// Main: one block per residue class r = n mod 625 (16 nodes share 512 rows).
// Stage A: gather the 512 x-rows into smem (coalesced, 1 line/instr).
// Stage B: warp w handles nodes nA = r+625w, nB = r+625(w+8).
//   lane = 16*dpar + c ; iteration t covers d = 2t+dpar.
//   weight addr  = i*WSTRIDE + 512n + 32t + lane   -> scalar LDG, 128B/warp
//   smem row     = 32t + lane                       -> per-lane full row read
// ---------------------------------------------------------------------------
__global__ __launch_bounds__(256, 3)
void lcg_main(const float* __restrict__ W, float* __restrict__ out) {
    extern __shared__ float sx[];               // [512][ROWPAD]
    const int r    = blockIdx.x;
    const int w    = threadIdx.x >> 5;          // warp 0..7
    const int lane = threadIdx.x & 31;

    // ---- Stage A: warp w stages rows w*64 .. w*64+63 (coalesced gathers)
    {
        const int fbase = w * 64;
        const int ev0 = g_e32[r * FLATS + fbase + lane];
        const int ev1 = g_e32[r * FLATS + fbase + 32 + lane];
#pragma unroll 8
        for (int k = 0; k < 64; ++k) {
            int src = __shfl_sync(0xffffffffu, (k < 32) ? ev0 : ev1, k & 31);
            float v = __ldg(&g_xT[src * 32 + lane]);     // one 128B line / warp
            sx[(fbase + k) * ROWPAD + lane] = v;
        }
    }
    __syncthreads();

    // ---- Stage B
    const int nA = r + NRES * w;
    const int nB = r + NRES * (w + 8);

    const float* __restrict__ WA = W + nA * FLATS + lane;   // + i*WSTRIDE + 32t
    const float* __restrict__ WB = W + nB * FLATS + lane;

    float accA[BATCH], accB[BATCH];
#pragma unroll
    for (int b = 0; b < BATCH; ++b) { accA[b] = 0.0f; accB[b] = 0.0f; }

#pragma unroll
    for (int t = 0; t < 16; ++t) {
        const int o = 32 * t;

        // 8 fully-coalesced scalar weight loads (128B per warp each)
        const float a0 = __ldcs(WA + o);
        const float a1 = __ldcs(WA + o + WSTRIDE);
        const float a2 = __ldcs(WA + o + 2 * WSTRIDE);
        const float a3 = __ldcs(WA + o + 3 * WSTRIDE);
        const float b0 = __ldcs(WB + o);
        const float b1 = __ldcs(WB + o + WSTRIDE);
        const float b2 = __ldcs(WB + o + 2 * WSTRIDE);
        const float b3 = __ldcs(WB + o + 3 * WSTRIDE);

        // this lane's x-row for (d = 2t+dpar, c): row = 32t + lane
        const float4* __restrict__ rp =
            reinterpret_cast<const float4*>(sx + (o + lane) * ROWPAD);

#pragma unroll
        for (int b = 0; b < BATCH; ++b) {
            float4 v = rp[b];    // x[b, src, 0..3] (16B-aligned: ROWPAD%4==0)
            accA[b] += v.x * a0 + v.y * a1 + v.z * a2 + v.w * a3;
            accB[b] += v.x * b0 + v.y * b1 + v.z * b2 + v.w * b3;
        }
    }

    // ---- combine the two d-parities (lane <-> lane^16), then write out
#pragma unroll
    for (int b = 0; b < BATCH; ++b) {
        accA[b] += __shfl_xor_sync(0xffffffffu, accA[b], 16);
        accB[b] += __shfl_xor_sync(0xffffffffu, accB[b], 16);
    }

    const int c    = lane & 15;
    const int half = lane >> 4;          // 0 -> batches 0..3, 1 -> batches 4..7
#pragma unroll
    for (int k = 0; k < 4; ++k) {
        const int b = half * 4 + k;
        out[b * OUTPLANE + nA * CH + c] = half ? accA[k + 4] : accA[k];
        out[b * OUTPLANE + nB * CH + c] = half ? accB[k + 4] : accB[k];
    }
}

// ---------------------------------------------------------------------------
// Launch
// ---------------------------------------------------------------------------
extern "C" void kernel_launch(void* const* d_in, const int* in_sizes, int n_in,
                              void* d_out, int out_size) {
    const float* x     = (const float*)d_in[0];   // (8,10000,4) f32
    const void*  edges = d_in[1];                 // (320000,) int64 or int32
    const float* W     = (const float*)d_in[2];   // (4,320000,16) f32
    float*       out   = (float*)d_out;           // (8,10000,16) f32
    (void)in_sizes; (void)n_in; (void)out_size;

    cudaFuncSetAttribute(lcg_main, cudaFuncAttributeMaxDynamicSharedMemorySize,
                         SMEM_BYTES);

    prep_kernel<<<320, 256>>>(x, edges);
    lcg_main<<<NRES, 256, SMEM_BYTES>>>(W, out);
}